// round 5
// baseline (speedup 1.0000x reference)
#include <cuda_runtime.h>

#define DD 4096
#define PLANE 4224   // 4096 + 128 pad floats per row

__device__ float g_dev[DD];

__global__ void compute_g_kernel(const float* __restrict__ eps,
                                 const float* __restrict__ g_mu,
                                 const float* __restrict__ g_rho) {
    int i = blockIdx.x * blockDim.x + threadIdx.x;
    if (i < DD) {
        float r = g_rho[i];
        g_dev[i] = g_mu[i] + log1pf(expf(r)) * eps[i];
    }
}

// Scalar radix-64 FWHT over the register index (6 butterfly stages).
__device__ __forceinline__ void fwht64(float v[64]) {
#pragma unroll
    for (int s = 0; s < 6; s++) {
        const int h = 1 << s;
#pragma unroll
        for (int q = 0; q < 64; q += 2*h) {
#pragma unroll
            for (int j = 0; j < h; j++) {
                float a = v[q+j], b = v[q+j+h];
                v[q+j]   = a + b;
                v[q+j+h] = a - b;
            }
        }
    }
}

// y = s1 * F( g * F( s2 * x ) ),  F_4096 = F_A (elem bits {0,1,7,8,9,10})
//                                        o F_B (elem bits {2,3,4,5,6,11})
// Each factor is a full radix-64 in-register transform -> ONE transpose:
//   P1: coalesced load, *s2, F_A, store
//   P2: load, F_B, *g, F_B, store
//   P3: load, F_A, *s1, coalesced store
// Shared layout: phys(i) = i + (i>>5) (pad 1 float per 32). Bank-injective
// per warp for both phase layouts, and base/offset sums never carry into
// bit 5, so phys(base+c) = phys(base) + phys(c): every LDS/STS address is
// base register + compile-time immediate (zero addressing ALU).
// 128 threads/CTA = 2 rows (64 threads each, own smem plane).
__global__ void __launch_bounds__(128)
whvi_kernel(const float* __restrict__ x,
            const float* __restrict__ s1,
            const float* __restrict__ s2,
            float* __restrict__ out) {
    __shared__ float sm[2 * PLANE];

    const int t = threadIdx.x;
    const int u = t & 63;                 // thread within row
    const int plane = (t >> 6) * PLANE;   // row-local smem plane

    // Phase A: lanes = elem bits {2..6} (u&31), bit 11 (u>>5); regs = rest.
    const int baseA = 4 * (u & 31) + 2048 * (u >> 5);
    const int physA = plane + baseA + (baseA >> 5);
    // Phase B: lanes = elem bits {0,1} (u&3), {7,8,9} ((u>>2)&7), {10} (u>>5).
    const int baseB = (u & 3) + 128 * ((u >> 2) & 7) + 1024 * (u >> 5);
    const int physB = plane + baseB + (baseB >> 5);

    const long long row = 2LL * blockIdx.x + (t >> 6);
    const float* xr = x + row * DD;

    float v[64];

    // ---- P1: coalesced float4 load, *s2, F_A, store ----
#pragma unroll
    for (int q = 0; q < 16; q++) {
        const float4 a = *reinterpret_cast<const float4*>(xr + baseA + 128*q);
        const float4 s = *reinterpret_cast<const float4*>(s2 + baseA + 128*q);
        v[4*q+0] = a.x * s.x;
        v[4*q+1] = a.y * s.y;
        v[4*q+2] = a.z * s.z;
        v[4*q+3] = a.w * s.w;
    }
    fwht64(v);
    // elem offset c(r) = (r&3) + 128*(r>>2); phys offset = (r&3) + 132*(r>>2)
#pragma unroll
    for (int r = 0; r < 64; r++)
        sm[physA + (r & 3) + 132 * (r >> 2)] = v[r];
    __syncthreads();

    // ---- P2: F_B, *g, F_B ----
    // elem offset c(r) = 4*(r&31) + 2048*(r>>5)
    // phys offset      = 4*(r&31) + ((r&31)>>3) + 2112*(r>>5)
#pragma unroll
    for (int r = 0; r < 64; r++)
        v[r] = sm[physB + 4*(r & 31) + ((r & 31) >> 3) + 2112*(r >> 5)];
    fwht64(v);
#pragma unroll
    for (int r = 0; r < 64; r++)
        v[r] *= g_dev[baseB + 4*(r & 31) + 2048*(r >> 5)];
    fwht64(v);
#pragma unroll
    for (int r = 0; r < 64; r++)
        sm[physB + 4*(r & 31) + ((r & 31) >> 3) + 2112*(r >> 5)] = v[r];
    __syncthreads();

    // ---- P3: load, F_A, *s1, coalesced float4 store ----
#pragma unroll
    for (int r = 0; r < 64; r++)
        v[r] = sm[physA + (r & 3) + 132 * (r >> 2)];
    fwht64(v);

    float* orow = out + row * DD;
#pragma unroll
    for (int q = 0; q < 16; q++) {
        const float4 s = *reinterpret_cast<const float4*>(s1 + baseA + 128*q);
        float4 o;
        o.x = v[4*q+0] * s.x;
        o.y = v[4*q+1] * s.y;
        o.z = v[4*q+2] * s.z;
        o.w = v[4*q+3] * s.w;
        *reinterpret_cast<float4*>(orow + baseA + 128*q) = o;
    }
}

extern "C" void kernel_launch(void* const* d_in, const int* in_sizes, int n_in,
                              void* d_out, int out_size) {
    const float* x     = (const float*)d_in[0];
    const float* eps   = (const float*)d_in[1];
    const float* s1    = (const float*)d_in[2];
    const float* s2    = (const float*)d_in[3];
    const float* g_mu  = (const float*)d_in[4];
    const float* g_rho = (const float*)d_in[5];
    float* out = (float*)d_out;

    int B = in_sizes[0] / DD;   // 2048

    compute_g_kernel<<<(DD + 255) / 256, 256>>>(eps, g_mu, g_rho);
    whvi_kernel<<<B / 2, 128>>>(x, s1, s2, out);
}

// round 6
// speedup vs baseline: 2.6790x; 2.6790x over previous
#include <cuda_runtime.h>

#define DD 4096
#define SMSZ 4224   // 4096 + 4096/32 pad floats

__device__ float g_dev[DD];

__global__ void compute_g_kernel(const float* __restrict__ eps,
                                 const float* __restrict__ g_mu,
                                 const float* __restrict__ g_rho) {
    int i = blockIdx.x * blockDim.x + threadIdx.x;
    if (i < DD) {
        float r = g_rho[i];
        g_dev[i] = g_mu[i] + log1pf(expf(r)) * eps[i];
    }
}

// Scalar radix-16 FWHT over the register index (4 butterfly stages).
__device__ __forceinline__ void fwht16(float v[16]) {
#pragma unroll
    for (int s = 0; s < 4; s++) {
        const int h = 1 << s;
#pragma unroll
        for (int q = 0; q < 16; q += 2*h) {
#pragma unroll
            for (int j = 0; j < h; j++) {
                float a = v[q+j], b = v[q+j+h];
                v[q+j]   = a + b;
                v[q+j+h] = a - b;
            }
        }
    }
}

// y_row = s1 * FWHT( g * FWHT( s2 * x_row ) ),  FWHT_4096 = F_A . F_B . F_C
// (same proven structure and bit assignments as the 45.6us R3 kernel):
//   Phase A: regs = bits {0..3},  lanes = bits {4..8},  warps = bits {9..11}
//   Phase B: regs = bits {4..7},  lanes = bits {0,1,2,8,9}, warps = {3,10,11}
//   Phase C: regs = bits {8..11}, lanes = bits {0..4},  warps = bits {5..7}
// NEW vs R3: additive carry-free pad swizzle phys(i) = i + (i>>5).
//   - bank-injective per warp for all three layouts (verified per layout)
//   - base&31 + offset&31 never carries, so phys(base+c) = physBase + physC
//     with physC compile-time -> every LDS/STS is [Rbase + immediate],
//     removing the per-access LOP3 the XOR swizzle required.
__global__ void __launch_bounds__(256, 5)
whvi_kernel(const float* __restrict__ x,
            const float* __restrict__ s1,
            const float* __restrict__ s2,
            float* __restrict__ out) {
    __shared__ float sm[SMSZ];

    const int t = threadIdx.x;
    const int l = t & 31;
    const int w = t >> 5;

    const int baseA = 16*l + 512*w;
    const int baseB = (l & 7) + 8*(w & 1) + 256*(l >> 3) + 1024*(w >> 1);
    const int baseC = l + 32*w;
    const int pA = baseA + (baseA >> 5);
    const int pB = baseB + (baseB >> 5);
    const int pC = baseC + (baseC >> 5);

    const long long row = blockIdx.x;
    const float* xr = x + row * DD;

    float v[16];

    // ---- P1: coalesced load, *s2, F_A ----
#pragma unroll
    for (int q = 0; q < 4; q++) {
        float4 a = *reinterpret_cast<const float4*>(xr + baseA + 4*q);
        float4 s = *reinterpret_cast<const float4*>(s2 + baseA + 4*q);
        v[4*q+0] = a.x * s.x;
        v[4*q+1] = a.y * s.y;
        v[4*q+2] = a.z * s.z;
        v[4*q+3] = a.w * s.w;
    }
    fwht16(v);
#pragma unroll
    for (int r = 0; r < 16; r++) sm[pA + r] = v[r];          // offset r
    __syncthreads();

    // ---- P2: F_B ----  elem offset 16r -> phys offset 16r + (r>>1)
#pragma unroll
    for (int r = 0; r < 16; r++) v[r] = sm[pB + 16*r + (r >> 1)];
    fwht16(v);
#pragma unroll
    for (int r = 0; r < 16; r++) sm[pB + 16*r + (r >> 1)] = v[r];
    __syncthreads();

    // ---- P3: F_C, *g, F_C ----  elem offset 256r -> phys offset 264r
#pragma unroll
    for (int r = 0; r < 16; r++) v[r] = sm[pC + 264*r];
    fwht16(v);
#pragma unroll
    for (int r = 0; r < 16; r++) v[r] *= g_dev[baseC + 256*r];
    fwht16(v);
#pragma unroll
    for (int r = 0; r < 16; r++) sm[pC + 264*r] = v[r];
    __syncthreads();

    // ---- P4: F_B ----
#pragma unroll
    for (int r = 0; r < 16; r++) v[r] = sm[pB + 16*r + (r >> 1)];
    fwht16(v);
#pragma unroll
    for (int r = 0; r < 16; r++) sm[pB + 16*r + (r >> 1)] = v[r];
    __syncthreads();

    // ---- P5: F_A, *s1, coalesced store ----
#pragma unroll
    for (int r = 0; r < 16; r++) v[r] = sm[pA + r];
    fwht16(v);

    float* orow = out + row * DD;
#pragma unroll
    for (int q = 0; q < 4; q++) {
        float4 s = *reinterpret_cast<const float4*>(s1 + baseA + 4*q);
        float4 o;
        o.x = v[4*q+0] * s.x;
        o.y = v[4*q+1] * s.y;
        o.z = v[4*q+2] * s.z;
        o.w = v[4*q+3] * s.w;
        *reinterpret_cast<float4*>(orow + baseA + 4*q) = o;
    }
}

extern "C" void kernel_launch(void* const* d_in, const int* in_sizes, int n_in,
                              void* d_out, int out_size) {
    const float* x     = (const float*)d_in[0];
    const float* eps   = (const float*)d_in[1];
    const float* s1    = (const float*)d_in[2];
    const float* s2    = (const float*)d_in[3];
    const float* g_mu  = (const float*)d_in[4];
    const float* g_rho = (const float*)d_in[5];
    float* out = (float*)d_out;

    int B = in_sizes[0] / DD;   // 2048

    compute_g_kernel<<<(DD + 255) / 256, 256>>>(eps, g_mu, g_rho);
    whvi_kernel<<<B, 256>>>(x, s1, s2, out);
}